// round 3
// baseline (speedup 1.0000x reference)
#include <cuda_runtime.h>

#define BB 16
#define NN 1024
#define DD 64
#define FIN 80
#define BN_EPS 1e-5f

// ---------------- scratch (device globals: no allocations allowed) ----------
__device__ float     g_h[BB*NN*DD];          // 4MB  node features
__device__ float     g_hW[BB*NN*DD];         // 4MB  relu(h @ Wl)
__device__ float     g_t1[BB*NN];
__device__ float     g_E1[BB*NN];
__device__ float2    g_te2[BB*NN];           // (t2, exp(t2))
__device__ unsigned  g_adjbits[BB*NN*(NN/32)];
__device__ float     g_Sall[BB*DD];          // per-batch column sums of hW

// ---------------- packed f32x2 helpers --------------------------------------
__device__ __forceinline__ unsigned long long pack2(float x, float y) {
    unsigned long long r;
    asm("mov.b64 %0, {%1, %2};" : "=l"(r) : "f"(x), "f"(y));
    return r;
}
__device__ __forceinline__ void unpack2(unsigned long long v, float &x, float &y) {
    asm("mov.b64 {%0, %1}, %2;" : "=f"(x), "=f"(y) : "l"(v));
}
__device__ __forceinline__ void ffma2(unsigned long long &d, unsigned long long a,
                                      unsigned long long b) {
    asm("fma.rn.f32x2 %0, %1, %2, %0;" : "+l"(d) : "l"(a), "l"(b));
}

// ---------------- kernel 1: pack adj into bitmask ---------------------------
__global__ void pack_adj_kernel(const int* __restrict__ adj) {
    int gt   = blockIdx.x * blockDim.x + threadIdx.x;
    int lane = gt & 31;
    int v = adj[gt];
    unsigned m = __ballot_sync(0xffffffffu, v > 0);
    if (lane == 0) g_adjbits[gt >> 5] = m;
}

// ---------------- kernel 2: h = relu(X @ W0), 32 rows/block ------------------
__global__ void __launch_bounds__(128) input_proj_kernel(const float* __restrict__ X,
                                                         const float* __restrict__ W0) {
    __shared__ float  xs[32 * FIN];       // 10KB
    __shared__ float2 wp[FIN * 32];       // 20KB
    int tid = threadIdx.x;
    int rowbase = blockIdx.x * 32;

    const float4* xsrc = (const float4*)(X + (size_t)rowbase * FIN);
    float4* xdst = (float4*)xs;
    #pragma unroll
    for (int t = 0; t < 5; ++t) xdst[tid + t * 128] = xsrc[tid + t * 128];

    for (int idx = tid; idx < FIN * 32; idx += 128) {
        int k = idx >> 5, l = idx & 31;
        wp[idx] = make_float2(W0[k * 64 + l], W0[k * 64 + l + 32]);
    }
    __syncthreads();

    int w = tid >> 5, lane = tid & 31;
    for (int j = 0; j < 8; ++j) {
        int row = w * 8 + j;
        const float* xr = xs + row * FIN;
        float a0 = 0.f, a1 = 0.f;
        #pragma unroll
        for (int k = 0; k < FIN; k += 4) {
            float4 x4 = *(const float4*)(xr + k);
            float2 w0 = wp[(k + 0) * 32 + lane];
            float2 w1 = wp[(k + 1) * 32 + lane];
            float2 w2 = wp[(k + 2) * 32 + lane];
            float2 w3 = wp[(k + 3) * 32 + lane];
            a0 = fmaf(x4.x, w0.x, a0); a1 = fmaf(x4.x, w0.y, a1);
            a0 = fmaf(x4.y, w1.x, a0); a1 = fmaf(x4.y, w1.y, a1);
            a0 = fmaf(x4.z, w2.x, a0); a1 = fmaf(x4.z, w2.y, a1);
            a0 = fmaf(x4.w, w3.x, a0); a1 = fmaf(x4.w, w3.y, a1);
        }
        int gr = rowbase + row;
        g_h[gr * 64 + lane]      = fmaxf(a0, 0.f);
        g_h[gr * 64 + lane + 32] = fmaxf(a1, 0.f);
    }
}

// ---------------- zero S_all -------------------------------------------------
__global__ void zero_sall_kernel() {
    int idx = blockIdx.x * 128 + threadIdx.x;
    if (idx < BB * DD) g_Sall[idx] = 0.f;
}

// ------- kernel 3: hW = relu(h@Wl[i]); t1,t2,E1,(t2,E2); S_all; 32 rows/block
__global__ void __launch_bounds__(128) hw_kernel(const float* __restrict__ Wl,
                                                 const float* __restrict__ a1l,
                                                 const float* __restrict__ a2l,
                                                 int li) {
    __shared__ float  hs[32 * 64];        // 8KB
    __shared__ float2 wp[64 * 32];        // 16KB
    int tid = threadIdx.x;
    int rowbase = blockIdx.x * 32;
    int b = rowbase >> 10;

    const float4* hsrc = (const float4*)(g_h + (size_t)rowbase * 64);
    float4* hdst = (float4*)hs;
    #pragma unroll
    for (int t = 0; t < 4; ++t) hdst[tid + t * 128] = hsrc[tid + t * 128];

    const float* W = Wl + li * 4096;
    for (int idx = tid; idx < 2048; idx += 128) {
        int k = idx >> 5, l = idx & 31;
        wp[idx] = make_float2(W[k * 64 + l], W[k * 64 + l + 32]);
    }
    __syncthreads();

    int w = tid >> 5, lane = tid & 31;
    float a1lo = a1l[li * 64 + lane], a1hi = a1l[li * 64 + lane + 32];
    float a2lo = a2l[li * 64 + lane], a2hi = a2l[li * 64 + lane + 32];
    float s0 = 0.f, s1 = 0.f;

    for (int j = 0; j < 8; ++j) {
        int row = w * 8 + j;
        const float* hr = hs + row * 64;
        float acc0 = 0.f, acc1 = 0.f;
        #pragma unroll
        for (int k = 0; k < 64; k += 4) {
            float4 h4 = *(const float4*)(hr + k);
            float2 w0 = wp[(k + 0) * 32 + lane];
            float2 w1 = wp[(k + 1) * 32 + lane];
            float2 w2 = wp[(k + 2) * 32 + lane];
            float2 w3 = wp[(k + 3) * 32 + lane];
            acc0 = fmaf(h4.x, w0.x, acc0); acc1 = fmaf(h4.x, w0.y, acc1);
            acc0 = fmaf(h4.y, w1.x, acc0); acc1 = fmaf(h4.y, w1.y, acc1);
            acc0 = fmaf(h4.z, w2.x, acc0); acc1 = fmaf(h4.z, w2.y, acc1);
            acc0 = fmaf(h4.w, w3.x, acc0); acc1 = fmaf(h4.w, w3.y, acc1);
        }
        acc0 = fmaxf(acc0, 0.f); acc1 = fmaxf(acc1, 0.f);
        int gr = rowbase + row;
        g_hW[gr * 64 + lane]      = acc0;
        g_hW[gr * 64 + lane + 32] = acc1;
        s0 += acc0; s1 += acc1;

        float p1 = fmaf(acc1, a1hi, acc0 * a1lo);
        float p2 = fmaf(acc1, a2hi, acc0 * a2lo);
        #pragma unroll
        for (int o = 16; o > 0; o >>= 1) {
            p1 += __shfl_down_sync(0xffffffffu, p1, o);
            p2 += __shfl_down_sync(0xffffffffu, p2, o);
        }
        if (lane == 0) {
            g_t1[gr]  = p1;
            g_E1[gr]  = __expf(p1);
            g_te2[gr] = make_float2(p2, __expf(p2));
        }
    }
    atomicAdd(&g_Sall[b * 64 + lane],      s0);
    atomicAdd(&g_Sall[b * 64 + lane + 32], s1);
}

// ---------------- kernel 4: tiled masked attention (SGEMM-style) ------------
// Block: 32 query rows x 64 d. 128 threads, thread tile 2n x 8d.
// coef(n,m) = (adjbit && t1[n]+t2[m]>0) ? E1[n]*E2[m]-1 : 0
// emb[n,:] = (S_all + sum_m coef*hW[m,:]) / (N + sum_m coef)
__global__ void __launch_bounds__(128) attn_kernel(const float* __restrict__ root_list,
                                                   int rootLayer) {
    __shared__ float              hw_s[32 * 64];        // 8KB (m-major)
    __shared__ unsigned long long coef_s[32 * 32];      // 8KB dup pairs [m][n]
    __shared__ float2             te_s[32];
    __shared__ float              z_s[4 * 32];

    int tid  = threadIdx.x;
    int b    = blockIdx.x >> 5;            // 16 batches
    int tile = blockIdx.x & 31;            // 32 row-tiles of 32
    int nbase = tile * 32;

    // coef-gen role: this thread owns row n_c, m-octet mq
    int n_c = tid & 31;
    int mq  = tid >> 5;                    // 0..3
    int grow = b * NN + nbase + n_c;
    float t1n = g_t1[grow];
    float E1n = g_E1[grow];
    const unsigned* awp = g_adjbits + (size_t)grow * 32;
    float zpart = 0.f;

    // matmul role: thread owns rows 2nq,2nq+1 and d-cols dq*8..dq*8+7
    int nq = tid >> 3;                     // 0..15
    int dq = tid & 7;                      // 0..7

    unsigned long long acc[8];
    #pragma unroll
    for (int k = 0; k < 8; ++k) acc[k] = 0ull;

    const float4* hwbase = (const float4*)(g_hW + (size_t)b * NN * DD);
    const float2* tebase = g_te2 + b * NN;

    for (int c = 0; c < 32; ++c) {
        __syncthreads();   // previous matmul reads done
        // stage hW chunk (32 m-rows x 64 d) + te2 chunk
        #pragma unroll
        for (int t = 0; t < 4; ++t)
            ((float4*)hw_s)[tid + t * 128] = hwbase[c * 512 + tid + t * 128];
        if (tid < 32) te_s[tid] = tebase[c * 32 + tid];
        unsigned aw = awp[c];
        __syncthreads();

        // coef tile generation: 8 coefs per thread
        #pragma unroll
        for (int i = 0; i < 8; ++i) {
            int ml = mq * 8 + i;
            float2 te = te_s[ml];
            bool p = ((aw >> ml) & 1u) && (t1n + te.x > 0.f);
            float cf = p ? fmaf(E1n, te.y, -1.f) : 0.f;
            zpart += cf;
            coef_s[ml * 32 + n_c] = pack2(cf, cf);
        }
        __syncthreads();

        // register-tile matmul over 32 m
        #pragma unroll 8
        for (int m = 0; m < 32; ++m) {
            ulonglong2 cp = *(const ulonglong2*)(coef_s + m * 32 + 2 * nq);
            const ulonglong2* hp = (const ulonglong2*)(hw_s + m * 64 + dq * 8);
            ulonglong2 h01 = hp[0];
            ulonglong2 h23 = hp[1];
            ffma2(acc[0], cp.x, h01.x);
            ffma2(acc[1], cp.x, h01.y);
            ffma2(acc[2], cp.x, h23.x);
            ffma2(acc[3], cp.x, h23.y);
            ffma2(acc[4], cp.y, h01.x);
            ffma2(acc[5], cp.y, h01.y);
            ffma2(acc[6], cp.y, h23.x);
            ffma2(acc[7], cp.y, h23.y);
        }
    }

    // reduce Z partials
    __syncthreads();
    z_s[mq * 32 + n_c] = zpart;
    __syncthreads();

    int n0 = 2 * nq, n1 = 2 * nq + 1;
    float Z0 = (float)NN + z_s[n0] + z_s[32 + n0] + z_s[64 + n0] + z_s[96 + n0];
    float Z1 = (float)NN + z_s[n1] + z_s[32 + n1] + z_s[64 + n1] + z_s[96 + n1];
    float invZ0 = __fdividef(1.f, Z0);
    float invZ1 = __fdividef(1.f, Z1);

    const float* rl = root_list + b * (4 * NN) + rootLayer * NN + nbase;
    const float* sall = g_Sall + b * 64 + dq * 8;
    float s0 = sall[0], s1 = sall[1], s2 = sall[2], s3 = sall[3];
    float s4 = sall[4], s5 = sall[5], s6 = sall[6], s7 = sall[7];

    if (rl[n0] > 0.f) {
        float* ho = g_h + ((size_t)b * NN + nbase + n0) * 64 + dq * 8;
        float x0, x1, x2, x3, x4, x5, x6, x7;
        unpack2(acc[0], x0, x1); unpack2(acc[1], x2, x3);
        unpack2(acc[2], x4, x5); unpack2(acc[3], x6, x7);
        float4 o0 = make_float4((s0 + x0) * invZ0, (s1 + x1) * invZ0,
                                (s2 + x2) * invZ0, (s3 + x3) * invZ0);
        float4 o1 = make_float4((s4 + x4) * invZ0, (s5 + x5) * invZ0,
                                (s6 + x6) * invZ0, (s7 + x7) * invZ0);
        ((float4*)ho)[0] = o0; ((float4*)ho)[1] = o1;
    }
    if (rl[n1] > 0.f) {
        float* ho = g_h + ((size_t)b * NN + nbase + n1) * 64 + dq * 8;
        float x0, x1, x2, x3, x4, x5, x6, x7;
        unpack2(acc[4], x0, x1); unpack2(acc[5], x2, x3);
        unpack2(acc[6], x4, x5); unpack2(acc[7], x6, x7);
        float4 o0 = make_float4((s0 + x0) * invZ1, (s1 + x1) * invZ1,
                                (s2 + x2) * invZ1, (s3 + x3) * invZ1);
        float4 o1 = make_float4((s4 + x4) * invZ1, (s5 + x5) * invZ1,
                                (s6 + x6) * invZ1, (s7 + x7) * invZ1);
        ((float4*)ho)[0] = o0; ((float4*)ho)[1] = o1;
    }
}

// ---------------- kernel 5: masked attention pool + BN-MLP head -------------
__global__ void __launch_bounds__(128) head_kernel(
    const float* __restrict__ root_list, const float* __restrict__ P,
    const float* __restrict__ pW1, const float* __restrict__ pb1,
    const float* __restrict__ g1,  const float* __restrict__ be1,
    const float* __restrict__ m1,  const float* __restrict__ v1,
    const float* __restrict__ pW2, const float* __restrict__ pb2,
    const float* __restrict__ g2,  const float* __restrict__ be2,
    const float* __restrict__ m2,  const float* __restrict__ v2,
    const float* __restrict__ pW3, const float* __restrict__ pb3,
    float* __restrict__ out) {

    __shared__ float  sh_w[NN];
    __shared__ float  sh_red[128];
    __shared__ float  sh_pool2[128];
    __shared__ float  sh_pool[64];
    __shared__ float  sh_x1[128];
    __shared__ float  sh_x2[64];
    __shared__ float4 sh_P[16];

    int b = blockIdx.x;
    int tid = threadIdx.x;
    if (tid < 16) sh_P[tid] = ((const float4*)P)[tid];
    __syncthreads();

    // phase 1: per-node scores -> weights
    float wsum = 0.f;
    for (int n = tid; n < NN; n += 128) {
        const float4* hr = (const float4*)(g_h + ((size_t)b * NN + n) * 64);
        float s = 0.f;
        #pragma unroll
        for (int k = 0; k < 16; ++k) {
            float4 h4 = hr[k]; float4 p4 = sh_P[k];
            s = fmaf(h4.x, p4.x, s);
            s = fmaf(h4.y, p4.y, s);
            s = fmaf(h4.z, p4.z, s);
            s = fmaf(h4.w, p4.w, s);
        }
        s = fmaxf(s, 0.f);
        float root = root_list[b * (4 * NN) + 1 * NN + n];
        float w = (root > 0.f) ? __expf(s) : 0.f;
        sh_w[n] = w;
        wsum += w;
    }
    sh_red[tid] = wsum;
    __syncthreads();
    for (int o = 64; o > 0; o >>= 1) {
        if (tid < o) sh_red[tid] += sh_red[tid + o];
        __syncthreads();
    }
    float invw = __fdividef(1.f, sh_red[0]);

    // phase 2: pooled vector, two threads per output dim (n split in half)
    {
        int d = tid & 63, half = tid >> 6;
        float acc = 0.f;
        const float* hb = g_h + (size_t)b * NN * 64 + (size_t)half * 512 * 64 + d;
        const float* wb = sh_w + half * 512;
        for (int n = 0; n < 512; ++n) acc = fmaf(wb[n], hb[n * 64], acc);
        sh_pool2[tid] = acc;
    }
    __syncthreads();
    if (tid < 64) sh_pool[tid] = (sh_pool2[tid] + sh_pool2[tid + 64]) * invw;
    __syncthreads();

    // MLP layer 1: 64 -> 128 with BN + relu
    {
        float acc = pb1[tid];
        #pragma unroll 8
        for (int k = 0; k < 64; ++k) acc = fmaf(sh_pool[k], pW1[k * 128 + tid], acc);
        float bnv = (acc - m1[tid]) * rsqrtf(v1[tid] + BN_EPS) * g1[tid] + be1[tid];
        sh_x1[tid] = fmaxf(bnv, 0.f);
    }
    __syncthreads();

    // MLP layer 2: 128 -> 64 with BN + relu
    if (tid < 64) {
        float acc = pb2[tid];
        #pragma unroll 8
        for (int k = 0; k < 128; ++k) acc = fmaf(sh_x1[k], pW2[k * 64 + tid], acc);
        float bnv = (acc - m2[tid]) * rsqrtf(v2[tid] + BN_EPS) * g2[tid] + be2[tid];
        sh_x2[tid] = fmaxf(bnv, 0.f);
    }
    __syncthreads();

    // MLP layer 3 + softmax(2)
    if (tid == 0) {
        float l0 = pb3[0], l1 = pb3[1];
        #pragma unroll 8
        for (int k = 0; k < 64; ++k) {
            l0 = fmaf(sh_x2[k], pW3[k * 2 + 0], l0);
            l1 = fmaf(sh_x2[k], pW3[k * 2 + 1], l1);
        }
        l0 = fmaxf(l0, 0.f); l1 = fmaxf(l1, 0.f);
        float mx = fmaxf(l0, l1);
        float e0 = __expf(l0 - mx), e1 = __expf(l1 - mx);
        float inv = __fdividef(1.f, e0 + e1);
        out[b * 2 + 0] = e0 * inv;
        out[b * 2 + 1] = e1 * inv;
    }
}

// ---------------- launch -----------------------------------------------------
extern "C" void kernel_launch(void* const* d_in, const int* in_sizes, int n_in,
                              void* d_out, int out_size) {
    const int*   adj       = (const int*)  d_in[0];
    const float* X         = (const float*)d_in[1];
    const float* root_list = (const float*)d_in[2];
    const float* W0        = (const float*)d_in[3];
    const float* Wl        = (const float*)d_in[4];
    const float* a1l       = (const float*)d_in[5];
    const float* a2l       = (const float*)d_in[6];
    const float* P         = (const float*)d_in[7];
    const float* pW1 = (const float*)d_in[8];  const float* pb1 = (const float*)d_in[9];
    const float* g1  = (const float*)d_in[10]; const float* be1 = (const float*)d_in[11];
    const float* m1  = (const float*)d_in[12]; const float* v1  = (const float*)d_in[13];
    const float* pW2 = (const float*)d_in[14]; const float* pb2 = (const float*)d_in[15];
    const float* g2  = (const float*)d_in[16]; const float* be2 = (const float*)d_in[17];
    const float* m2  = (const float*)d_in[18]; const float* v2  = (const float*)d_in[19];
    const float* pW3 = (const float*)d_in[20]; const float* pb3 = (const float*)d_in[21];
    float* out = (float*)d_out;

    pack_adj_kernel<<<BB * NN * NN / 256, 256>>>(adj);
    input_proj_kernel<<<BB * NN / 32, 128>>>(X, W0);

    for (int li = 0; li < 3; ++li) {
        zero_sall_kernel<<<8, 128>>>();
        hw_kernel<<<BB * NN / 32, 128>>>(Wl, a1l, a2l, li);
        attn_kernel<<<BB * 32, 128>>>(root_list, 3 - li);
    }

    head_kernel<<<BB, 128>>>(root_list, P,
                             pW1, pb1, g1, be1, m1, v1,
                             pW2, pb2, g2, be2, m2, v2,
                             pW3, pb3, out);
}

// round 5
// speedup vs baseline: 1.7440x; 1.7440x over previous
#include <cuda_runtime.h>
#include <cstdint>

#define BB 16
#define NN 1024
#define DD 64
#define FIN 80
#define BN_EPS 1e-5f

typedef unsigned long long ull;

// ---------------- scratch globals -------------------------------------------
__device__ float    g_h[BB*NN*DD];          // node features fp32
__device__ float    g_hW[BB*NN*DD];         // relu(h @ Wl)
__device__ float2   g_t1e1[BB*NN];          // (t1, exp(t1))
__device__ float2   g_te2[BB*NN];           // (t2, exp(t2))
__device__ unsigned g_adjT[BB*32*NN];       // transposed bitmask [b][word][n]
__device__ float    g_Sall[BB*DD];          // per-batch column sums of hW

// ---------------- packed f32x2 helpers --------------------------------------
__device__ __forceinline__ ull pack2(float x, float y) {
    ull r;
    asm("mov.b64 %0, {%1, %2};" : "=l"(r) : "f"(x), "f"(y));
    return r;
}
__device__ __forceinline__ void unpack2(ull v, float &x, float &y) {
    asm("mov.b64 {%0, %1}, %2;" : "=f"(x), "=f"(y) : "l"(v));
}
__device__ __forceinline__ void ffma2(ull &d, ull a, ull b) {
    asm("fma.rn.f32x2 %0, %1, %2, %0;" : "+l"(d) : "l"(a), "l"(b));
}

// ---------------- kernel 1: pack adj into transposed bitmask ----------------
__global__ void __launch_bounds__(256) pack_adj_kernel(const int* __restrict__ adj) {
    __shared__ unsigned tw[32 * 128];      // [word][n_local]
    int b  = blockIdx.x >> 3;
    int nt = blockIdx.x & 7;
    int tid = threadIdx.x;
    int w   = tid >> 5;
    int lane = tid & 31;

    for (int j = 0; j < 16; ++j) {
        int nl = w * 16 + j;
        const int* rowp = adj + ((size_t)(b * NN + nt * 128 + nl)) * NN;
        #pragma unroll 4
        for (int c = 0; c < 32; ++c) {
            int v = rowp[c * 32 + lane];
            unsigned m = __ballot_sync(0xffffffffu, v > 0);
            if (lane == 0) tw[c * 128 + nl] = m;
        }
    }
    __syncthreads();
    for (int i = tid; i < 4096; i += 256) {
        int c = i >> 7, nl = i & 127;
        g_adjT[(size_t)(b * 32 + c) * NN + nt * 128 + nl] = tw[i];
    }
}

// ---------------- kernel 2: h = relu(X @ W0), 64 rows / 256 thr --------------
__global__ void __launch_bounds__(256) input_proj_kernel(const float* __restrict__ X,
                                                         const float* __restrict__ W0) {
    __shared__ float  xs[64 * FIN];       // 20KB
    __shared__ float2 wp[FIN * 32];       // 20KB
    int tid = threadIdx.x;
    int rowbase = blockIdx.x * 64;

    const float4* xsrc = (const float4*)(X + (size_t)rowbase * FIN);
    float4* xdst = (float4*)xs;
    #pragma unroll
    for (int t = 0; t < 5; ++t) xdst[tid + t * 256] = xsrc[tid + t * 256];

    for (int idx = tid; idx < FIN * 32; idx += 256) {
        int k = idx >> 5, l = idx & 31;
        wp[idx] = make_float2(W0[k * 64 + l], W0[k * 64 + l + 32]);
    }
    __syncthreads();

    int w = tid >> 5, lane = tid & 31;
    for (int j = 0; j < 8; ++j) {
        int row = w * 8 + j;
        const float* xr = xs + row * FIN;
        float a0 = 0.f, a1 = 0.f;
        #pragma unroll
        for (int k = 0; k < FIN; k += 4) {
            float4 x4 = *(const float4*)(xr + k);
            float2 w0 = wp[(k + 0) * 32 + lane];
            float2 w1 = wp[(k + 1) * 32 + lane];
            float2 w2 = wp[(k + 2) * 32 + lane];
            float2 w3 = wp[(k + 3) * 32 + lane];
            a0 = fmaf(x4.x, w0.x, a0); a1 = fmaf(x4.x, w0.y, a1);
            a0 = fmaf(x4.y, w1.x, a0); a1 = fmaf(x4.y, w1.y, a1);
            a0 = fmaf(x4.z, w2.x, a0); a1 = fmaf(x4.z, w2.y, a1);
            a0 = fmaf(x4.w, w3.x, a0); a1 = fmaf(x4.w, w3.y, a1);
        }
        int gr = rowbase + row;
        g_h[gr * 64 + lane]      = fmaxf(a0, 0.f);
        g_h[gr * 64 + lane + 32] = fmaxf(a1, 0.f);
    }
}

__global__ void zero_sall_kernel() {
    int idx = blockIdx.x * 128 + threadIdx.x;
    if (idx < BB * DD) g_Sall[idx] = 0.f;
}

// ---- kernel 3: hW = relu(h@Wl); t1/t2/exp via 2-shfl + smem phase2 ---------
__global__ void __launch_bounds__(256) hw_kernel(const float* __restrict__ Wl,
                                                 const float* __restrict__ a1l,
                                                 const float* __restrict__ a2l,
                                                 int li) {
    __shared__ float  hs[64 * 64];        // 16KB
    __shared__ float2 wp[64 * 32];        // 16KB
    __shared__ float2 pt[64 * 9];         // 4.5KB partials (8 lanes/row)
    int tid = threadIdx.x;
    int rowbase = blockIdx.x * 64;
    int b = rowbase >> 10;

    const float4* hsrc = (const float4*)(g_h + (size_t)rowbase * 64);
    float4* hdst = (float4*)hs;
    #pragma unroll
    for (int t = 0; t < 4; ++t) hdst[tid + t * 256] = hsrc[tid + t * 256];

    const float* W = Wl + li * 4096;
    for (int idx = tid; idx < 2048; idx += 256) {
        int k = idx >> 5, l = idx & 31;
        wp[idx] = make_float2(W[k * 64 + l], W[k * 64 + l + 32]);
    }
    __syncthreads();

    int w = tid >> 5, lane = tid & 31;
    float a1lo = a1l[li * 64 + lane], a1hi = a1l[li * 64 + lane + 32];
    float a2lo = a2l[li * 64 + lane], a2hi = a2l[li * 64 + lane + 32];
    float s0 = 0.f, s1 = 0.f;

    for (int j = 0; j < 8; ++j) {
        int row = w * 8 + j;
        const float* hr = hs + row * 64;
        float acc0 = 0.f, acc1 = 0.f;
        #pragma unroll
        for (int k = 0; k < 64; k += 4) {
            float4 h4 = *(const float4*)(hr + k);
            float2 w0 = wp[(k + 0) * 32 + lane];
            float2 w1 = wp[(k + 1) * 32 + lane];
            float2 w2 = wp[(k + 2) * 32 + lane];
            float2 w3 = wp[(k + 3) * 32 + lane];
            acc0 = fmaf(h4.x, w0.x, acc0); acc1 = fmaf(h4.x, w0.y, acc1);
            acc0 = fmaf(h4.y, w1.x, acc0); acc1 = fmaf(h4.y, w1.y, acc1);
            acc0 = fmaf(h4.z, w2.x, acc0); acc1 = fmaf(h4.z, w2.y, acc1);
            acc0 = fmaf(h4.w, w3.x, acc0); acc1 = fmaf(h4.w, w3.y, acc1);
        }
        acc0 = fmaxf(acc0, 0.f); acc1 = fmaxf(acc1, 0.f);
        int gr = rowbase + row;
        g_hW[gr * 64 + lane]      = acc0;
        g_hW[gr * 64 + lane + 32] = acc1;
        s0 += acc0; s1 += acc1;

        float p1 = fmaf(acc1, a1hi, acc0 * a1lo);
        float p2 = fmaf(acc1, a2hi, acc0 * a2lo);
        p1 += __shfl_down_sync(0xffffffffu, p1, 16);
        p2 += __shfl_down_sync(0xffffffffu, p2, 16);
        p1 += __shfl_down_sync(0xffffffffu, p1, 8);
        p2 += __shfl_down_sync(0xffffffffu, p2, 8);
        if (lane < 8) pt[row * 9 + lane] = make_float2(p1, p2);
    }
    atomicAdd(&g_Sall[b * 64 + lane],      s0);
    atomicAdd(&g_Sall[b * 64 + lane + 32], s1);

    __syncthreads();
    if (tid < 64) {
        int row = tid;
        float p1 = 0.f, p2 = 0.f;
        #pragma unroll
        for (int k = 0; k < 8; ++k) {
            float2 q = pt[row * 9 + k];
            p1 += q.x; p2 += q.y;
        }
        int gr = rowbase + row;
        g_t1e1[gr] = make_float2(p1, __expf(p1));
        g_te2[gr]  = make_float2(p2, __expf(p2));
    }
}

// ---------------- kernel 4: tiled masked attention (FFMA2 SGEMM) ------------
// CTA: 128 n-rows x 64 d, 512 threads. thread tile = 4n x 4d.
// coef(n,m) = (adjbit && t1[n]+t2[m]>0) ? E1[n]*E2[m]-1 : 0
// emb[n,:] = (Sall + sum_m coef*hW[m,:]) / (N + sum_m coef)
__global__ void __launch_bounds__(512) attn_kernel(const float* __restrict__ root_list,
                                                   int rootLayer) {
    __shared__ float2 t1e1_s[128];          // 1KB
    __shared__ float  sall_s[64];
    __shared__ float  root_s[128];
    __shared__ float  z_s[4 * 128];         // 2KB
    __shared__ ull    coef_s[32 * 128];     // 32KB  [m][n] duplicated pairs
    __shared__ float  hw_s[32 * 64];        // 8KB   [m][d]

    int tid = threadIdx.x;
    int b   = blockIdx.x >> 3;
    int nt  = blockIdx.x & 7;
    int nbase = nt * 128;

    // ---- init staging ----
    if (tid < 128) {
        t1e1_s[tid] = g_t1e1[b * NN + nbase + tid];
        root_s[tid] = root_list[b * (4 * NN) + rootLayer * NN + nbase + tid];
    } else if (tid < 192) {
        sall_s[tid - 128] = g_Sall[b * 64 + (tid - 128)];
    }

    // gen role
    int gn = tid & 127;
    int mh = tid >> 7;                    // 0..3 (m-octet)
    float zpart = 0.f;

    // matmul role: n-rows nq*4.., d-cols dq*4..
    int nq = tid >> 4;                    // 0..31
    int dq = tid & 15;                    // 0..15

    ull acc[4][2];
    #pragma unroll
    for (int i = 0; i < 4; ++i) { acc[i][0] = 0ull; acc[i][1] = 0ull; }

    const float4* hwbase = (const float4*)(g_hW + (size_t)b * NN * DD);
    const float2* te_g   = g_te2 + b * NN;
    const unsigned* awcol = g_adjT + (size_t)b * 32 * NN + nbase;

    __syncthreads();

    for (int c = 0; c < 32; ++c) {
        // prev matmul finished -> coef_s/hw_s free (also covers init staging)
        // stage hW chunk: 32m x 64d = 512 float4, one per thread
        {
            int m = tid >> 4, d4 = tid & 15;
            ((float4*)hw_s)[m * 16 + d4] = hwbase[(c * 32 + m) * 16 + d4];
        }
        // gen coef tile for 8 m values (reads te2/adj straight from global)
        {
            float2 t1e1 = t1e1_s[gn];
            unsigned aw = awcol[(size_t)c * NN + gn];
            #pragma unroll
            for (int j = 0; j < 8; ++j) {
                int m = mh * 8 + j;
                float2 te = te_g[c * 32 + m];
                bool p = ((aw >> m) & 1u) && (t1e1.x + te.x > 0.f);
                float cf = p ? fmaf(t1e1.y, te.y, -1.f) : 0.f;
                zpart += cf;
                coef_s[m * 128 + gn] = pack2(cf, cf);
            }
        }
        __syncthreads();

        // matmul: 32 m, 8 FFMA2 each
        #pragma unroll
        for (int m = 0; m < 32; ++m) {
            const ulonglong2* cp = (const ulonglong2*)(coef_s + m * 128 + nq * 4);
            ulonglong2 ca = cp[0];
            ulonglong2 cb = cp[1];
            ulonglong2 h  = *(const ulonglong2*)(hw_s + m * 64 + dq * 4);
            ffma2(acc[0][0], ca.x, h.x); ffma2(acc[0][1], ca.x, h.y);
            ffma2(acc[1][0], ca.y, h.x); ffma2(acc[1][1], ca.y, h.y);
            ffma2(acc[2][0], cb.x, h.x); ffma2(acc[2][1], cb.x, h.y);
            ffma2(acc[3][0], cb.y, h.x); ffma2(acc[3][1], cb.y, h.y);
        }
        __syncthreads();
    }

    // ---- Z reduction ----
    z_s[mh * 128 + gn] = zpart;
    __syncthreads();

    // ---- epilogue: 4 rows x 4 d per thread ----
    float s0 = sall_s[dq * 4 + 0], s1 = sall_s[dq * 4 + 1];
    float s2 = sall_s[dq * 4 + 2], s3 = sall_s[dq * 4 + 3];

    #pragma unroll
    for (int i = 0; i < 4; ++i) {
        int n = nq * 4 + i;
        if (root_s[n] > 0.f) {
            float Z = (float)NN + z_s[n] + z_s[128 + n] + z_s[256 + n] + z_s[384 + n];
            float invZ = __fdividef(1.f, Z);
            float x0, x1, x2, x3;
            unpack2(acc[i][0], x0, x1);
            unpack2(acc[i][1], x2, x3);
            float4 o = make_float4((s0 + x0) * invZ, (s1 + x1) * invZ,
                                   (s2 + x2) * invZ, (s3 + x3) * invZ);
            *(float4*)(g_h + ((size_t)b * NN + nbase + n) * 64 + dq * 4) = o;
        }
    }
}

// ---------------- kernel 5: masked attention pool + BN-MLP head -------------
__global__ void __launch_bounds__(128) head_kernel(
    const float* __restrict__ root_list, const float* __restrict__ P,
    const float* __restrict__ pW1, const float* __restrict__ pb1,
    const float* __restrict__ g1,  const float* __restrict__ be1,
    const float* __restrict__ m1,  const float* __restrict__ v1,
    const float* __restrict__ pW2, const float* __restrict__ pb2,
    const float* __restrict__ g2,  const float* __restrict__ be2,
    const float* __restrict__ m2,  const float* __restrict__ v2,
    const float* __restrict__ pW3, const float* __restrict__ pb3,
    float* __restrict__ out) {

    __shared__ float  sh_w[NN];
    __shared__ float  sh_red[128];
    __shared__ float  sh_pool2[128];
    __shared__ float  sh_pool[64];
    __shared__ float  sh_x1[128];
    __shared__ float  sh_x2[64];
    __shared__ float4 sh_P[16];

    int b = blockIdx.x;
    int tid = threadIdx.x;
    if (tid < 16) sh_P[tid] = ((const float4*)P)[tid];
    __syncthreads();

    float wsum = 0.f;
    for (int n = tid; n < NN; n += 128) {
        const float4* hr = (const float4*)(g_h + ((size_t)b * NN + n) * 64);
        float s = 0.f;
        #pragma unroll
        for (int k = 0; k < 16; ++k) {
            float4 h4 = hr[k]; float4 p4 = sh_P[k];
            s = fmaf(h4.x, p4.x, s);
            s = fmaf(h4.y, p4.y, s);
            s = fmaf(h4.z, p4.z, s);
            s = fmaf(h4.w, p4.w, s);
        }
        s = fmaxf(s, 0.f);
        float root = root_list[b * (4 * NN) + 1 * NN + n];
        float wv = (root > 0.f) ? __expf(s) : 0.f;
        sh_w[n] = wv;
        wsum += wv;
    }
    sh_red[tid] = wsum;
    __syncthreads();
    for (int o = 64; o > 0; o >>= 1) {
        if (tid < o) sh_red[tid] += sh_red[tid + o];
        __syncthreads();
    }
    float invw = __fdividef(1.f, sh_red[0]);

    {
        int d = tid & 63, half = tid >> 6;
        float acc = 0.f;
        const float* hb = g_h + (size_t)b * NN * 64 + (size_t)half * 512 * 64 + d;
        const float* wb = sh_w + half * 512;
        for (int n = 0; n < 512; ++n) acc = fmaf(wb[n], hb[n * 64], acc);
        sh_pool2[tid] = acc;
    }
    __syncthreads();
    if (tid < 64) sh_pool[tid] = (sh_pool2[tid] + sh_pool2[tid + 64]) * invw;
    __syncthreads();

    {
        float acc = pb1[tid];
        #pragma unroll 8
        for (int k = 0; k < 64; ++k) acc = fmaf(sh_pool[k], pW1[k * 128 + tid], acc);
        float bnv = (acc - m1[tid]) * rsqrtf(v1[tid] + BN_EPS) * g1[tid] + be1[tid];
        sh_x1[tid] = fmaxf(bnv, 0.f);
    }
    __syncthreads();

    if (tid < 64) {
        float acc = pb2[tid];
        #pragma unroll 8
        for (int k = 0; k < 128; ++k) acc = fmaf(sh_x1[k], pW2[k * 64 + tid], acc);
        float bnv = (acc - m2[tid]) * rsqrtf(v2[tid] + BN_EPS) * g2[tid] + be2[tid];
        sh_x2[tid] = fmaxf(bnv, 0.f);
    }
    __syncthreads();

    if (tid == 0) {
        float l0 = pb3[0], l1 = pb3[1];
        #pragma unroll 8
        for (int k = 0; k < 64; ++k) {
            l0 = fmaf(sh_x2[k], pW3[k * 2 + 0], l0);
            l1 = fmaf(sh_x2[k], pW3[k * 2 + 1], l1);
        }
        l0 = fmaxf(l0, 0.f); l1 = fmaxf(l1, 0.f);
        float mx = fmaxf(l0, l1);
        float e0 = __expf(l0 - mx), e1 = __expf(l1 - mx);
        float inv = __fdividef(1.f, e0 + e1);
        out[b * 2 + 0] = e0 * inv;
        out[b * 2 + 1] = e1 * inv;
    }
}

// ---------------- launch -----------------------------------------------------
extern "C" void kernel_launch(void* const* d_in, const int* in_sizes, int n_in,
                              void* d_out, int out_size) {
    const int*   adj       = (const int*)  d_in[0];
    const float* X         = (const float*)d_in[1];
    const float* root_list = (const float*)d_in[2];
    const float* W0        = (const float*)d_in[3];
    const float* Wl        = (const float*)d_in[4];
    const float* a1l       = (const float*)d_in[5];
    const float* a2l       = (const float*)d_in[6];
    const float* P         = (const float*)d_in[7];
    const float* pW1 = (const float*)d_in[8];  const float* pb1 = (const float*)d_in[9];
    const float* g1  = (const float*)d_in[10]; const float* be1 = (const float*)d_in[11];
    const float* m1  = (const float*)d_in[12]; const float* v1  = (const float*)d_in[13];
    const float* pW2 = (const float*)d_in[14]; const float* pb2 = (const float*)d_in[15];
    const float* g2  = (const float*)d_in[16]; const float* be2 = (const float*)d_in[17];
    const float* m2  = (const float*)d_in[18]; const float* v2  = (const float*)d_in[19];
    const float* pW3 = (const float*)d_in[20]; const float* pb3 = (const float*)d_in[21];
    float* out = (float*)d_out;

    pack_adj_kernel<<<BB * 8, 256>>>(adj);
    input_proj_kernel<<<BB * NN / 64, 256>>>(X, W0);

    for (int li = 0; li < 3; ++li) {
        zero_sall_kernel<<<8, 128>>>();
        hw_kernel<<<BB * NN / 64, 256>>>(Wl, a1l, a2l, li);
        attn_kernel<<<BB * 8, 512>>>(root_list, 3 - li);
    }

    head_kernel<<<BB, 128>>>(root_list, P,
                             pW1, pb1, g1, be1, m1, v1,
                             pW2, pb2, g2, be2, m2, v2,
                             pW3, pb3, out);
}

// round 6
// speedup vs baseline: 1.8809x; 1.0785x over previous
#include <cuda_runtime.h>
#include <cstdint>

#define BB 16
#define NN 1024
#define DD 64
#define FIN 80
#define BN_EPS 1e-5f

typedef unsigned long long ull;

// ---------------- scratch globals -------------------------------------------
__device__ float    g_h[BB*NN*DD];          // node features fp32
__device__ float    g_hW[BB*NN*DD];         // relu(h @ Wl)
__device__ float2   g_t1e1[BB*NN];          // (t1, exp(t1))
__device__ float2   g_te2[BB*NN];           // (t2, exp(t2))
__device__ unsigned g_adjT[BB*32*NN];       // transposed bitmask [b][word][n]
__device__ float    g_Sall3[3*BB*DD];       // per-layer column sums of hW

// ---------------- packed f32x2 helpers --------------------------------------
__device__ __forceinline__ ull pack2(float x, float y) {
    ull r;
    asm("mov.b64 %0, {%1, %2};" : "=l"(r) : "f"(x), "f"(y));
    return r;
}
__device__ __forceinline__ void unpack2(ull v, float &x, float &y) {
    asm("mov.b64 {%0, %1}, %2;" : "=f"(x), "=f"(y) : "l"(v));
}
__device__ __forceinline__ void ffma2(ull &d, ull a, ull b) {
    asm("fma.rn.f32x2 %0, %1, %2, %0;" : "+l"(d) : "l"(a), "l"(b));
}

// ---------------- kernel 1: pack adj (transposed bitmask) + zero Sall -------
__global__ void __launch_bounds__(256) pack_adj_kernel(const int* __restrict__ adj) {
    __shared__ unsigned tw[32 * 128];      // [word][n_local]
    int b  = blockIdx.x >> 3;
    int nt = blockIdx.x & 7;
    int tid = threadIdx.x;
    int w   = tid >> 5;
    int lane = tid & 31;

    if (blockIdx.x == 0) {
        for (int i = tid; i < 3 * BB * DD; i += 256) g_Sall3[i] = 0.f;
    }

    for (int j = 0; j < 16; ++j) {
        int nl = w * 16 + j;
        const int* rowp = adj + ((size_t)(b * NN + nt * 128 + nl)) * NN;
        #pragma unroll 4
        for (int c = 0; c < 32; ++c) {
            int v = rowp[c * 32 + lane];
            unsigned m = __ballot_sync(0xffffffffu, v > 0);
            if (lane == 0) tw[c * 128 + nl] = m;
        }
    }
    __syncthreads();
    for (int i = tid; i < 4096; i += 256) {
        int c = i >> 7, nl = i & 127;
        g_adjT[(size_t)(b * 32 + c) * NN + nt * 128 + nl] = tw[i];
    }
}

// ---------------- kernel 2: h = relu(X @ W0), 64 rows / 256 thr --------------
__global__ void __launch_bounds__(256) input_proj_kernel(const float* __restrict__ X,
                                                         const float* __restrict__ W0) {
    __shared__ float  xs[64 * FIN];
    __shared__ float2 wp[FIN * 32];
    int tid = threadIdx.x;
    int rowbase = blockIdx.x * 64;

    const float4* xsrc = (const float4*)(X + (size_t)rowbase * FIN);
    float4* xdst = (float4*)xs;
    #pragma unroll
    for (int t = 0; t < 5; ++t) xdst[tid + t * 256] = xsrc[tid + t * 256];

    for (int idx = tid; idx < FIN * 32; idx += 256) {
        int k = idx >> 5, l = idx & 31;
        wp[idx] = make_float2(W0[k * 64 + l], W0[k * 64 + l + 32]);
    }
    __syncthreads();

    int w = tid >> 5, lane = tid & 31;
    for (int j = 0; j < 8; ++j) {
        int row = w * 8 + j;
        const float* xr = xs + row * FIN;
        float a0 = 0.f, a1 = 0.f;
        #pragma unroll
        for (int k = 0; k < FIN; k += 4) {
            float4 x4 = *(const float4*)(xr + k);
            float2 w0 = wp[(k + 0) * 32 + lane];
            float2 w1 = wp[(k + 1) * 32 + lane];
            float2 w2 = wp[(k + 2) * 32 + lane];
            float2 w3 = wp[(k + 3) * 32 + lane];
            a0 = fmaf(x4.x, w0.x, a0); a1 = fmaf(x4.x, w0.y, a1);
            a0 = fmaf(x4.y, w1.x, a0); a1 = fmaf(x4.y, w1.y, a1);
            a0 = fmaf(x4.z, w2.x, a0); a1 = fmaf(x4.z, w2.y, a1);
            a0 = fmaf(x4.w, w3.x, a0); a1 = fmaf(x4.w, w3.y, a1);
        }
        int gr = rowbase + row;
        g_h[gr * 64 + lane]      = fmaxf(a0, 0.f);
        g_h[gr * 64 + lane + 32] = fmaxf(a1, 0.f);
    }
}

// ---- kernel 3: hW = relu(h@Wl); t1/t2/exp; Sall (layer-indexed) ------------
__global__ void __launch_bounds__(256) hw_kernel(const float* __restrict__ Wl,
                                                 const float* __restrict__ a1l,
                                                 const float* __restrict__ a2l,
                                                 int li) {
    __shared__ float  hs[64 * 64];
    __shared__ float2 wp[64 * 32];
    __shared__ float2 pt[64 * 9];
    int tid = threadIdx.x;
    int rowbase = blockIdx.x * 64;
    int b = rowbase >> 10;

    const float4* hsrc = (const float4*)(g_h + (size_t)rowbase * 64);
    float4* hdst = (float4*)hs;
    #pragma unroll
    for (int t = 0; t < 4; ++t) hdst[tid + t * 256] = hsrc[tid + t * 256];

    const float* W = Wl + li * 4096;
    for (int idx = tid; idx < 2048; idx += 256) {
        int k = idx >> 5, l = idx & 31;
        wp[idx] = make_float2(W[k * 64 + l], W[k * 64 + l + 32]);
    }
    __syncthreads();

    int w = tid >> 5, lane = tid & 31;
    float a1lo = a1l[li * 64 + lane], a1hi = a1l[li * 64 + lane + 32];
    float a2lo = a2l[li * 64 + lane], a2hi = a2l[li * 64 + lane + 32];
    float s0 = 0.f, s1 = 0.f;

    for (int j = 0; j < 8; ++j) {
        int row = w * 8 + j;
        const float* hr = hs + row * 64;
        float acc0 = 0.f, acc1 = 0.f;
        #pragma unroll
        for (int k = 0; k < 64; k += 4) {
            float4 h4 = *(const float4*)(hr + k);
            float2 w0 = wp[(k + 0) * 32 + lane];
            float2 w1 = wp[(k + 1) * 32 + lane];
            float2 w2 = wp[(k + 2) * 32 + lane];
            float2 w3 = wp[(k + 3) * 32 + lane];
            acc0 = fmaf(h4.x, w0.x, acc0); acc1 = fmaf(h4.x, w0.y, acc1);
            acc0 = fmaf(h4.y, w1.x, acc0); acc1 = fmaf(h4.y, w1.y, acc1);
            acc0 = fmaf(h4.z, w2.x, acc0); acc1 = fmaf(h4.z, w2.y, acc1);
            acc0 = fmaf(h4.w, w3.x, acc0); acc1 = fmaf(h4.w, w3.y, acc1);
        }
        acc0 = fmaxf(acc0, 0.f); acc1 = fmaxf(acc1, 0.f);
        int gr = rowbase + row;
        g_hW[gr * 64 + lane]      = acc0;
        g_hW[gr * 64 + lane + 32] = acc1;
        s0 += acc0; s1 += acc1;

        float p1 = fmaf(acc1, a1hi, acc0 * a1lo);
        float p2 = fmaf(acc1, a2hi, acc0 * a2lo);
        p1 += __shfl_down_sync(0xffffffffu, p1, 16);
        p2 += __shfl_down_sync(0xffffffffu, p2, 16);
        p1 += __shfl_down_sync(0xffffffffu, p1, 8);
        p2 += __shfl_down_sync(0xffffffffu, p2, 8);
        if (lane < 8) pt[row * 9 + lane] = make_float2(p1, p2);
    }
    float* sall = g_Sall3 + li * (BB * DD);
    atomicAdd(&sall[b * 64 + lane],      s0);
    atomicAdd(&sall[b * 64 + lane + 32], s1);

    __syncthreads();
    if (tid < 64) {
        int row = tid;
        float p1 = 0.f, p2 = 0.f;
        #pragma unroll
        for (int k = 0; k < 8; ++k) {
            float2 q = pt[row * 9 + k];
            p1 += q.x; p2 += q.y;
        }
        int gr = rowbase + row;
        g_t1e1[gr] = make_float2(p1, __expf(p1));
        g_te2[gr]  = make_float2(p2, __expf(p2));
    }
}

// ---------------- kernel 4: double-buffered masked attention (FFMA2) --------
// CTA: 128 n x 64 d, 512 threads, thread tile 4n x 4d.
// Pipeline: prefetch LDG(c+1) -> matmul(c) -> gen(c+1) -> 1 barrier.
#define SM_COEF   0          // [2][32][128] ull  = 65536
#define SM_HW     65536      // [2][32*64] float  = 16384
#define SM_TE     81920      // [1024] float2     = 8192
#define SM_T1E1   90112      // [128] float2      = 1024
#define SM_SALL   91136      // [64] float        = 256
#define SM_ROOT   91392      // [128] float       = 512
#define SM_Z      91904      // [512] float       = 2048
#define SM_ATTN_TOTAL 93952

__global__ void __launch_bounds__(512) attn_kernel(const float* __restrict__ root_list,
                                                   int rootLayer, int li) {
    extern __shared__ char smem[];
    ull*    coef_s = (ull*)(smem + SM_COEF);
    float*  hw_s   = (float*)(smem + SM_HW);
    float2* te_s   = (float2*)(smem + SM_TE);
    float2* t1e1_s = (float2*)(smem + SM_T1E1);
    float*  sall_s = (float*)(smem + SM_SALL);
    float*  root_s = (float*)(smem + SM_ROOT);
    float*  z_s    = (float*)(smem + SM_Z);

    int tid = threadIdx.x;
    int b   = blockIdx.x >> 3;
    int nt  = blockIdx.x & 7;
    int nbase = nt * 128;

    // roles
    int gn = tid & 127;                  // gen: n row
    int mh = tid >> 7;                   // gen: m-octet 0..3
    int nq = tid >> 4;                   // matmul: 4n rows at nq*4
    int dq = tid & 15;                   // matmul: 4d cols at dq*4
    // stage role: m = nq, d4 = dq

    const float4*  hwbase = (const float4*)(g_hW + (size_t)b * NN * DD);
    const float2*  te_g   = g_te2 + b * NN;
    const unsigned* awcol = g_adjT + (size_t)b * 32 * NN + nbase;

    // ---- init staging ----
    #pragma unroll
    for (int t = 0; t < 2; ++t) te_s[tid + t * 512] = te_g[tid + t * 512];
    if (tid < 128) {
        t1e1_s[tid] = g_t1e1[b * NN + nbase + tid];
        root_s[tid] = root_list[b * (4 * NN) + rootLayer * NN + nbase + tid];
    } else if (tid < 192) {
        sall_s[tid - 128] = g_Sall3[li * (BB * DD) + b * 64 + (tid - 128)];
    }
    float4   pf_hw = hwbase[nq * 16 + dq];          // chunk 0
    unsigned pf_aw = awcol[gn];                      // chunk 0
    __syncthreads();                                 // te_s/t1e1_s ready

    float zpart = 0.f;
    // gen chunk 0 into buf 0
    {
        ((float4*)hw_s)[tid] = pf_hw;
        float2 t1e1 = t1e1_s[gn];
        #pragma unroll
        for (int j = 0; j < 8; ++j) {
            int m = mh * 8 + j;
            float2 te = te_s[m];
            bool p = ((pf_aw >> m) & 1u) && (t1e1.x + te.x > 0.f);
            float cf = p ? fmaf(t1e1.y, te.y, -1.f) : 0.f;
            zpart += cf;
            coef_s[m * 128 + gn] = pack2(cf, cf);
        }
    }
    __syncthreads();

    ull acc[4][2];
    #pragma unroll
    for (int i = 0; i < 4; ++i) { acc[i][0] = 0ull; acc[i][1] = 0ull; }

    #pragma unroll 1
    for (int c = 0; c < 32; ++c) {
        int buf = c & 1;
        // prefetch next chunk's globals (hidden behind matmul)
        if (c < 31) {
            pf_hw = hwbase[((c + 1) * 32 + nq) * 16 + dq];
            pf_aw = awcol[(size_t)(c + 1) * NN + gn];
        }

        // matmul on current buffer: 32 m, 8 FFMA2 each
        const ull*   cbuf = coef_s + buf * (32 * 128);
        const float* hbuf = hw_s + buf * (32 * 64);
        #pragma unroll
        for (int m = 0; m < 32; ++m) {
            const ulonglong2* cp = (const ulonglong2*)(cbuf + m * 128 + nq * 4);
            ulonglong2 ca = cp[0];
            ulonglong2 cb = cp[1];
            ulonglong2 h  = *(const ulonglong2*)(hbuf + m * 64 + dq * 4);
            ffma2(acc[0][0], ca.x, h.x); ffma2(acc[0][1], ca.x, h.y);
            ffma2(acc[1][0], ca.y, h.x); ffma2(acc[1][1], ca.y, h.y);
            ffma2(acc[2][0], cb.x, h.x); ffma2(acc[2][1], cb.x, h.y);
            ffma2(acc[3][0], cb.y, h.x); ffma2(acc[3][1], cb.y, h.y);
        }

        // gen next chunk into other buffer
        if (c < 31) {
            int nbuf = buf ^ 1;
            ((float4*)(hw_s + nbuf * (32 * 64)))[tid] = pf_hw;
            ull* ncoef = coef_s + nbuf * (32 * 128);
            float2 t1e1 = t1e1_s[gn];
            #pragma unroll
            for (int j = 0; j < 8; ++j) {
                int m = mh * 8 + j;
                float2 te = te_s[(c + 1) * 32 + m];
                bool p = ((pf_aw >> m) & 1u) && (t1e1.x + te.x > 0.f);
                float cf = p ? fmaf(t1e1.y, te.y, -1.f) : 0.f;
                zpart += cf;
                ncoef[m * 128 + gn] = pack2(cf, cf);
            }
        }
        __syncthreads();
    }

    // ---- Z reduction ----
    z_s[mh * 128 + gn] = zpart;
    __syncthreads();

    // ---- epilogue: 4 rows x 4 d per thread ----
    float s0 = sall_s[dq * 4 + 0], s1 = sall_s[dq * 4 + 1];
    float s2 = sall_s[dq * 4 + 2], s3 = sall_s[dq * 4 + 3];

    #pragma unroll
    for (int i = 0; i < 4; ++i) {
        int n = nq * 4 + i;
        if (root_s[n] > 0.f) {
            float Z = (float)NN + z_s[n] + z_s[128 + n] + z_s[256 + n] + z_s[384 + n];
            float invZ = __fdividef(1.f, Z);
            float x0, x1, x2, x3;
            unpack2(acc[i][0], x0, x1);
            unpack2(acc[i][1], x2, x3);
            float4 o = make_float4((s0 + x0) * invZ, (s1 + x1) * invZ,
                                   (s2 + x2) * invZ, (s3 + x3) * invZ);
            *(float4*)(g_h + ((size_t)b * NN + nbase + n) * 64 + dq * 4) = o;
        }
    }
}

// ---------------- kernel 5: masked attention pool + BN-MLP head -------------
__global__ void __launch_bounds__(128) head_kernel(
    const float* __restrict__ root_list, const float* __restrict__ P,
    const float* __restrict__ pW1, const float* __restrict__ pb1,
    const float* __restrict__ g1,  const float* __restrict__ be1,
    const float* __restrict__ m1,  const float* __restrict__ v1,
    const float* __restrict__ pW2, const float* __restrict__ pb2,
    const float* __restrict__ g2,  const float* __restrict__ be2,
    const float* __restrict__ m2,  const float* __restrict__ v2,
    const float* __restrict__ pW3, const float* __restrict__ pb3,
    float* __restrict__ out) {

    __shared__ float  sh_w[NN];
    __shared__ float  sh_red[128];
    __shared__ float4 sh_part[8 * 16];     // [grp][dq]
    __shared__ float  sh_pool[64];
    __shared__ float  sh_x1[128];
    __shared__ float  sh_x2[64];
    __shared__ float4 sh_P[16];

    int b = blockIdx.x;
    int tid = threadIdx.x;
    if (tid < 16) sh_P[tid] = ((const float4*)P)[tid];
    __syncthreads();

    // phase 1: per-node weights
    float wsum = 0.f;
    for (int n = tid; n < NN; n += 128) {
        const float4* hr = (const float4*)(g_h + ((size_t)b * NN + n) * 64);
        float s = 0.f;
        #pragma unroll
        for (int k = 0; k < 16; ++k) {
            float4 h4 = hr[k]; float4 p4 = sh_P[k];
            s = fmaf(h4.x, p4.x, s);
            s = fmaf(h4.y, p4.y, s);
            s = fmaf(h4.z, p4.z, s);
            s = fmaf(h4.w, p4.w, s);
        }
        s = fmaxf(s, 0.f);
        float root = root_list[b * (4 * NN) + 1 * NN + n];
        float wv = (root > 0.f) ? __expf(s) : 0.f;
        sh_w[n] = wv;
        wsum += wv;
    }
    sh_red[tid] = wsum;
    __syncthreads();
    for (int o = 64; o > 0; o >>= 1) {
        if (tid < o) sh_red[tid] += sh_red[tid + o];
        __syncthreads();
    }
    float invw = __fdividef(1.f, sh_red[0]);

    // phase 2: pooled vector, coalesced row reads
    {
        int dq = tid & 15, grp = tid >> 4;
        const float4* hb = (const float4*)(g_h + (size_t)b * NN * 64);
        float4 a = make_float4(0.f, 0.f, 0.f, 0.f);
        #pragma unroll 4
        for (int it = 0; it < 128; ++it) {
            int n = grp + it * 8;
            float wv = sh_w[n];
            float4 h4 = hb[n * 16 + dq];
            a.x = fmaf(wv, h4.x, a.x);
            a.y = fmaf(wv, h4.y, a.y);
            a.z = fmaf(wv, h4.z, a.z);
            a.w = fmaf(wv, h4.w, a.w);
        }
        sh_part[grp * 16 + dq] = a;
    }
    __syncthreads();
    if (tid < 64) {
        int dq = tid >> 2, comp = tid & 3;
        float acc = 0.f;
        #pragma unroll
        for (int g = 0; g < 8; ++g) {
            const float* p = (const float*)&sh_part[g * 16 + dq];
            acc += p[comp];
        }
        sh_pool[dq * 4 + comp] = acc * invw;
    }
    __syncthreads();

    // MLP 1: 64 -> 128, BN, relu
    {
        float acc = pb1[tid];
        #pragma unroll 8
        for (int k = 0; k < 64; ++k) acc = fmaf(sh_pool[k], pW1[k * 128 + tid], acc);
        float bnv = (acc - m1[tid]) * rsqrtf(v1[tid] + BN_EPS) * g1[tid] + be1[tid];
        sh_x1[tid] = fmaxf(bnv, 0.f);
    }
    __syncthreads();

    // MLP 2: 128 -> 64, BN, relu
    if (tid < 64) {
        float acc = pb2[tid];
        #pragma unroll 8
        for (int k = 0; k < 128; ++k) acc = fmaf(sh_x1[k], pW2[k * 64 + tid], acc);
        float bnv = (acc - m2[tid]) * rsqrtf(v2[tid] + BN_EPS) * g2[tid] + be2[tid];
        sh_x2[tid] = fmaxf(bnv, 0.f);
    }
    __syncthreads();

    // MLP 3 + softmax(2)
    if (tid == 0) {
        float l0 = pb3[0], l1 = pb3[1];
        #pragma unroll 8
        for (int k = 0; k < 64; ++k) {
            l0 = fmaf(sh_x2[k], pW3[k * 2 + 0], l0);
            l1 = fmaf(sh_x2[k], pW3[k * 2 + 1], l1);
        }
        l0 = fmaxf(l0, 0.f); l1 = fmaxf(l1, 0.f);
        float mx = fmaxf(l0, l1);
        float e0 = __expf(l0 - mx), e1 = __expf(l1 - mx);
        float inv = __fdividef(1.f, e0 + e1);
        out[b * 2 + 0] = e0 * inv;
        out[b * 2 + 1] = e1 * inv;
    }
}

// ---------------- launch -----------------------------------------------------
extern "C" void kernel_launch(void* const* d_in, const int* in_sizes, int n_in,
                              void* d_out, int out_size) {
    const int*   adj       = (const int*)  d_in[0];
    const float* X         = (const float*)d_in[1];
    const float* root_list = (const float*)d_in[2];
    const float* W0        = (const float*)d_in[3];
    const float* Wl        = (const float*)d_in[4];
    const float* a1l       = (const float*)d_in[5];
    const float* a2l       = (const float*)d_in[6];
    const float* P         = (const float*)d_in[7];
    const float* pW1 = (const float*)d_in[8];  const float* pb1 = (const float*)d_in[9];
    const float* g1  = (const float*)d_in[10]; const float* be1 = (const float*)d_in[11];
    const float* m1  = (const float*)d_in[12]; const float* v1  = (const float*)d_in[13];
    const float* pW2 = (const float*)d_in[14]; const float* pb2 = (const float*)d_in[15];
    const float* g2  = (const float*)d_in[16]; const float* be2 = (const float*)d_in[17];
    const float* m2  = (const float*)d_in[18]; const float* v2  = (const float*)d_in[19];
    const float* pW3 = (const float*)d_in[20]; const float* pb3 = (const float*)d_in[21];
    float* out = (float*)d_out;

    cudaFuncSetAttribute(attn_kernel, cudaFuncAttributeMaxDynamicSharedMemorySize,
                         SM_ATTN_TOTAL);

    pack_adj_kernel<<<BB * 8, 256>>>(adj);
    input_proj_kernel<<<BB * NN / 64, 256>>>(X, W0);

    for (int li = 0; li < 3; ++li) {
        hw_kernel<<<BB * NN / 64, 256>>>(Wl, a1l, a2l, li);
        attn_kernel<<<BB * 8, 512, SM_ATTN_TOTAL>>>(root_list, 3 - li, li);
    }

    head_kernel<<<BB, 128>>>(root_list, P,
                             pW1, pb1, g1, be1, m1, v1,
                             pW2, pb2, g2, be2, m2, v2,
                             pW3, pb3, out);
}

// round 7
// speedup vs baseline: 2.2353x; 1.1884x over previous
#include <cuda_runtime.h>
#include <cstdint>

#define BB 16
#define NN 1024
#define DD 64
#define FIN 80
#define BN_EPS 1e-5f

typedef unsigned long long ull;

// ---------------- scratch globals -------------------------------------------
__device__ float    g_h[BB*NN*DD];          // node features fp32
__device__ float    g_hW[BB*NN*DD];         // relu(h @ Wl)
__device__ float2   g_t1e1[BB*NN];          // (t1, exp(t1))
__device__ float2   g_te2[BB*NN];           // (t2, exp(t2))
__device__ unsigned g_adjT[BB*32*NN];       // transposed bitmask [b][word][n]
__device__ float    g_Sall3[3*BB*DD];       // per-layer column sums of hW

// ---------------- packed f32x2 helpers --------------------------------------
__device__ __forceinline__ ull pack2(float x, float y) {
    ull r;
    asm("mov.b64 %0, {%1, %2};" : "=l"(r) : "f"(x), "f"(y));
    return r;
}
__device__ __forceinline__ void unpack2(ull v, float &x, float &y) {
    asm("mov.b64 {%0, %1}, %2;" : "=f"(x), "=f"(y) : "l"(v));
}
__device__ __forceinline__ void ffma2(ull &d, ull a, ull b) {
    asm("fma.rn.f32x2 %0, %1, %2, %0;" : "+l"(d) : "l"(a), "l"(b));
}
__device__ __forceinline__ ull addf2(ull a, ull b) {
    ull r;
    asm("add.rn.f32x2 %0, %1, %2;" : "=l"(r) : "l"(a), "l"(b));
    return r;
}

// ---------------- kernel 1: pack adj (transposed bitmask) + zero Sall -------
__global__ void __launch_bounds__(256) pack_adj_kernel(const int* __restrict__ adj) {
    __shared__ unsigned tw[32 * 128];      // [word][n_local]
    int b  = blockIdx.x >> 3;
    int nt = blockIdx.x & 7;
    int tid = threadIdx.x;
    int w   = tid >> 5;
    int lane = tid & 31;

    if (blockIdx.x == 0) {
        for (int i = tid; i < 3 * BB * DD; i += 256) g_Sall3[i] = 0.f;
    }

    for (int j = 0; j < 16; ++j) {
        int nl = w * 16 + j;
        const int* rowp = adj + ((size_t)(b * NN + nt * 128 + nl)) * NN;
        #pragma unroll 4
        for (int c = 0; c < 32; ++c) {
            int v = rowp[c * 32 + lane];
            unsigned m = __ballot_sync(0xffffffffu, v > 0);
            if (lane == 0) tw[c * 128 + nl] = m;
        }
    }
    __syncthreads();
    for (int i = tid; i < 4096; i += 256) {
        int c = i >> 7, nl = i & 127;
        g_adjT[(size_t)(b * 32 + c) * NN + nt * 128 + nl] = tw[i];
    }
}

// ---------------- kernel 2: h = relu(X @ W0), 64 rows / 256 thr --------------
__global__ void __launch_bounds__(256) input_proj_kernel(const float* __restrict__ X,
                                                         const float* __restrict__ W0) {
    __shared__ float  xs[64 * FIN];
    __shared__ float2 wp[FIN * 32];
    int tid = threadIdx.x;
    int rowbase = blockIdx.x * 64;

    const float4* xsrc = (const float4*)(X + (size_t)rowbase * FIN);
    float4* xdst = (float4*)xs;
    #pragma unroll
    for (int t = 0; t < 5; ++t) xdst[tid + t * 256] = xsrc[tid + t * 256];

    for (int idx = tid; idx < FIN * 32; idx += 256) {
        int k = idx >> 5, l = idx & 31;
        wp[idx] = make_float2(W0[k * 64 + l], W0[k * 64 + l + 32]);
    }
    __syncthreads();

    int w = tid >> 5, lane = tid & 31;
    for (int j = 0; j < 8; ++j) {
        int row = w * 8 + j;
        const float* xr = xs + row * FIN;
        float a0 = 0.f, a1 = 0.f;
        #pragma unroll
        for (int k = 0; k < FIN; k += 4) {
            float4 x4 = *(const float4*)(xr + k);
            float2 w0 = wp[(k + 0) * 32 + lane];
            float2 w1 = wp[(k + 1) * 32 + lane];
            float2 w2 = wp[(k + 2) * 32 + lane];
            float2 w3 = wp[(k + 3) * 32 + lane];
            a0 = fmaf(x4.x, w0.x, a0); a1 = fmaf(x4.x, w0.y, a1);
            a0 = fmaf(x4.y, w1.x, a0); a1 = fmaf(x4.y, w1.y, a1);
            a0 = fmaf(x4.z, w2.x, a0); a1 = fmaf(x4.z, w2.y, a1);
            a0 = fmaf(x4.w, w3.x, a0); a1 = fmaf(x4.w, w3.y, a1);
        }
        int gr = rowbase + row;
        g_h[gr * 64 + lane]      = fmaxf(a0, 0.f);
        g_h[gr * 64 + lane + 32] = fmaxf(a1, 0.f);
    }
}

// ---- kernel 3: hW = relu(h@Wl); t1/t2/exp; Sall (layer-indexed) ------------
__global__ void __launch_bounds__(256) hw_kernel(const float* __restrict__ Wl,
                                                 const float* __restrict__ a1l,
                                                 const float* __restrict__ a2l,
                                                 int li) {
    __shared__ float  hs[64 * 64];
    __shared__ float2 wp[64 * 32];
    __shared__ float2 pt[64 * 9];
    int tid = threadIdx.x;
    int rowbase = blockIdx.x * 64;
    int b = rowbase >> 10;

    const float4* hsrc = (const float4*)(g_h + (size_t)rowbase * 64);
    float4* hdst = (float4*)hs;
    #pragma unroll
    for (int t = 0; t < 4; ++t) hdst[tid + t * 256] = hsrc[tid + t * 256];

    const float* W = Wl + li * 4096;
    for (int idx = tid; idx < 2048; idx += 256) {
        int k = idx >> 5, l = idx & 31;
        wp[idx] = make_float2(W[k * 64 + l], W[k * 64 + l + 32]);
    }
    __syncthreads();

    int w = tid >> 5, lane = tid & 31;
    float a1lo = a1l[li * 64 + lane], a1hi = a1l[li * 64 + lane + 32];
    float a2lo = a2l[li * 64 + lane], a2hi = a2l[li * 64 + lane + 32];
    float s0 = 0.f, s1 = 0.f;

    for (int j = 0; j < 8; ++j) {
        int row = w * 8 + j;
        const float* hr = hs + row * 64;
        float acc0 = 0.f, acc1 = 0.f;
        #pragma unroll
        for (int k = 0; k < 64; k += 4) {
            float4 h4 = *(const float4*)(hr + k);
            float2 w0 = wp[(k + 0) * 32 + lane];
            float2 w1 = wp[(k + 1) * 32 + lane];
            float2 w2 = wp[(k + 2) * 32 + lane];
            float2 w3 = wp[(k + 3) * 32 + lane];
            acc0 = fmaf(h4.x, w0.x, acc0); acc1 = fmaf(h4.x, w0.y, acc1);
            acc0 = fmaf(h4.y, w1.x, acc0); acc1 = fmaf(h4.y, w1.y, acc1);
            acc0 = fmaf(h4.z, w2.x, acc0); acc1 = fmaf(h4.z, w2.y, acc1);
            acc0 = fmaf(h4.w, w3.x, acc0); acc1 = fmaf(h4.w, w3.y, acc1);
        }
        acc0 = fmaxf(acc0, 0.f); acc1 = fmaxf(acc1, 0.f);
        int gr = rowbase + row;
        g_hW[gr * 64 + lane]      = acc0;
        g_hW[gr * 64 + lane + 32] = acc1;
        s0 += acc0; s1 += acc1;

        float p1 = fmaf(acc1, a1hi, acc0 * a1lo);
        float p2 = fmaf(acc1, a2hi, acc0 * a2lo);
        p1 += __shfl_down_sync(0xffffffffu, p1, 16);
        p2 += __shfl_down_sync(0xffffffffu, p2, 16);
        p1 += __shfl_down_sync(0xffffffffu, p1, 8);
        p2 += __shfl_down_sync(0xffffffffu, p2, 8);
        if (lane < 8) pt[row * 9 + lane] = make_float2(p1, p2);
    }
    float* sall = g_Sall3 + li * (BB * DD);
    atomicAdd(&sall[b * 64 + lane],      s0);
    atomicAdd(&sall[b * 64 + lane + 32], s1);

    __syncthreads();
    if (tid < 64) {
        int row = tid;
        float p1 = 0.f, p2 = 0.f;
        #pragma unroll
        for (int k = 0; k < 8; ++k) {
            float2 q = pt[row * 9 + k];
            p1 += q.x; p2 += q.y;
        }
        int gr = rowbase + row;
        g_t1e1[gr] = make_float2(p1, __expf(p1));
        g_te2[gr]  = make_float2(p2, __expf(p2));
    }
}

// ---------------- kernel 4: 4-group balanced attention (FFMA2, 8n x 8d) -----
// CTA: 512 thr = 4 m-groups x 128 thr. Each group: 128n x 64d tile, 8 chunks
// of 32 m, double-buffered; thread tile 8n x 8d (nq=wt>>3, dq=wt&7).
// coef stored non-dup f32 [m][n]; hW stored permuted: [m][p][dq16] so the
// matmul's two LDS.128 per operand are bank-conflict-free.
#define SM_COEF   0          // f32[4][2][32*128] = 131072
#define SM_HWP    131072     // f32[4][2][32*64]  = 65536
#define SM_TE     196608     // float2[1024]      = 8192
#define SM_T1E1   204800     // float2[128]       = 1024
#define SM_ROOT   205824     // f32[128]          = 512
#define SM_SALL   206336     // f32[64]           = 256
#define SM_Z      206592     // f32[4][128]       = 2048
#define SM_ATTN_TOTAL 208640

__global__ void __launch_bounds__(512, 1) attn_kernel(const float* __restrict__ root_list,
                                                      int rootLayer, int li) {
    extern __shared__ char smem[];
    float*  coef_s = (float*)(smem + SM_COEF);
    float*  hwp_s  = (float*)(smem + SM_HWP);
    float2* te_s   = (float2*)(smem + SM_TE);
    float2* t1e1_s = (float2*)(smem + SM_T1E1);
    float*  root_s = (float*)(smem + SM_ROOT);
    float*  sall_s = (float*)(smem + SM_SALL);
    float*  z_s    = (float*)(smem + SM_Z);

    int tid = threadIdx.x;
    int gid = tid >> 7;                  // m-group 0..3
    int wt  = tid & 127;                 // thread within group
    int b   = blockIdx.x >> 3;
    int nt  = blockIdx.x & 7;
    int nbase = nt * 128;

    int nq = wt >> 3;                    // 0..15 -> n rows nq*8..+7
    int dq = wt & 7;                     // 0..7  -> d cols dq*8..+7

    const float4*   hwbase = (const float4*)(g_hW + (size_t)b * NN * DD);
    const float2*   te_g   = g_te2 + b * NN;
    const unsigned* awcol  = g_adjT + (size_t)b * 32 * NN + nbase;

    // ---- prefetch chunk 0 of this group ----
    unsigned pf_aw;
    float4 pf_hw[4];
    {
        int c = gid * 8;
        pf_aw = awcol[(size_t)c * NN + wt];
        #pragma unroll
        for (int t = 0; t < 4; ++t) {
            int i = wt + t * 128;
            pf_hw[t] = hwbase[(c * 32 + (i >> 4)) * 16 + (i & 15)];
        }
    }

    // ---- CTA-wide staging ----
    #pragma unroll
    for (int t = 0; t < 2; ++t) te_s[tid + t * 512] = te_g[tid + t * 512];
    if (tid < 128) {
        t1e1_s[tid] = g_t1e1[b * NN + nbase + tid];
        root_s[tid] = root_list[b * (4 * NN) + rootLayer * NN + nbase + tid];
    } else if (tid < 192) {
        sall_s[tid - 128] = g_Sall3[li * (BB * DD) + b * 64 + (tid - 128)];
    }
    __syncthreads();

    float zpart = 0.f;

    // stage+gen chunk 0 into buf 0
    {
        float* hb = hwp_s + (gid * 2 + 0) * 2048;
        #pragma unroll
        for (int t = 0; t < 4; ++t) {
            int i = wt + t * 128;
            int m = i >> 4, d16 = i & 15;
            *(float4*)(hb + m * 64 + (d16 & 1) * 32 + (d16 >> 1) * 4) = pf_hw[t];
        }
        float* cb = coef_s + (gid * 2 + 0) * 4096;
        float2 t1e1 = t1e1_s[wt];
        int c = gid * 8;
        #pragma unroll 8
        for (int m = 0; m < 32; ++m) {
            float2 te = te_s[c * 32 + m];
            bool p = ((pf_aw >> m) & 1u) && (t1e1.x + te.x > 0.f);
            float cf = p ? fmaf(t1e1.y, te.y, -1.f) : 0.f;
            zpart += cf;
            cb[m * 128 + wt] = cf;
        }
    }
    asm volatile("bar.sync %0, %1;" :: "r"(gid + 1), "r"(128) : "memory");

    ull acc[32];
    #pragma unroll
    for (int i = 0; i < 32; ++i) acc[i] = 0ull;

    #pragma unroll 1
    for (int cg = 0; cg < 8; ++cg) {
        int buf = cg & 1;

        // prefetch next chunk
        if (cg < 7) {
            int c = gid * 8 + cg + 1;
            pf_aw = awcol[(size_t)c * NN + wt];
            #pragma unroll
            for (int t = 0; t < 4; ++t) {
                int i = wt + t * 128;
                pf_hw[t] = hwbase[(c * 32 + (i >> 4)) * 16 + (i & 15)];
            }
        }

        // ---- matmul on current buffer ----
        {
            const float* cb = coef_s + (gid * 2 + buf) * 4096;
            const float* hb = hwp_s + (gid * 2 + buf) * 2048;
            #pragma unroll 4
            for (int m = 0; m < 32; ++m) {
                float4 c0 = *(const float4*)(cb + m * 128 + nq * 8);
                float4 c1 = *(const float4*)(cb + m * 128 + nq * 8 + 4);
                ulonglong2 hA = *(const ulonglong2*)(hb + m * 64 + dq * 4);
                ulonglong2 hB = *(const ulonglong2*)(hb + m * 64 + 32 + dq * 4);
                ull cd;
                cd = pack2(c0.x, c0.x);
                ffma2(acc[0],  cd, hA.x); ffma2(acc[1],  cd, hA.y);
                ffma2(acc[2],  cd, hB.x); ffma2(acc[3],  cd, hB.y);
                cd = pack2(c0.y, c0.y);
                ffma2(acc[4],  cd, hA.x); ffma2(acc[5],  cd, hA.y);
                ffma2(acc[6],  cd, hB.x); ffma2(acc[7],  cd, hB.y);
                cd = pack2(c0.z, c0.z);
                ffma2(acc[8],  cd, hA.x); ffma2(acc[9],  cd, hA.y);
                ffma2(acc[10], cd, hB.x); ffma2(acc[11], cd, hB.y);
                cd = pack2(c0.w, c0.w);
                ffma2(acc[12], cd, hA.x); ffma2(acc[13], cd, hA.y);
                ffma2(acc[14], cd, hB.x); ffma2(acc[15], cd, hB.y);
                cd = pack2(c1.x, c1.x);
                ffma2(acc[16], cd, hA.x); ffma2(acc[17], cd, hA.y);
                ffma2(acc[18], cd, hB.x); ffma2(acc[19], cd, hB.y);
                cd = pack2(c1.y, c1.y);
                ffma2(acc[20], cd, hA.x); ffma2(acc[21], cd, hA.y);
                ffma2(acc[22], cd, hB.x); ffma2(acc[23], cd, hB.y);
                cd = pack2(c1.z, c1.z);
                ffma2(acc[24], cd, hA.x); ffma2(acc[25], cd, hA.y);
                ffma2(acc[26], cd, hB.x); ffma2(acc[27], cd, hB.y);
                cd = pack2(c1.w, c1.w);
                ffma2(acc[28], cd, hA.x); ffma2(acc[29], cd, hA.y);
                ffma2(acc[30], cd, hB.x); ffma2(acc[31], cd, hB.y);
            }
        }

        // ---- stage+gen next chunk into other buffer ----
        if (cg < 7) {
            int nbuf = buf ^ 1;
            float* hb = hwp_s + (gid * 2 + nbuf) * 2048;
            #pragma unroll
            for (int t = 0; t < 4; ++t) {
                int i = wt + t * 128;
                int m = i >> 4, d16 = i & 15;
                *(float4*)(hb + m * 64 + (d16 & 1) * 32 + (d16 >> 1) * 4) = pf_hw[t];
            }
            float* cb = coef_s + (gid * 2 + nbuf) * 4096;
            float2 t1e1 = t1e1_s[wt];
            int c = gid * 8 + cg + 1;
            #pragma unroll 8
            for (int m = 0; m < 32; ++m) {
                float2 te = te_s[c * 32 + m];
                bool p = ((pf_aw >> m) & 1u) && (t1e1.x + te.x > 0.f);
                float cf = p ? fmaf(t1e1.y, te.y, -1.f) : 0.f;
                zpart += cf;
                cb[m * 128 + wt] = cf;
            }
        }
        asm volatile("bar.sync %0, %1;" :: "r"(gid + 1), "r"(128) : "memory");
    }

    // ---- cross-group reduction ----
    z_s[gid * 128 + wt] = zpart;
    __syncthreads();

    if (gid != 0) {
        ull* dump = (ull*)(smem + SM_COEF) + (size_t)(gid - 1) * 4096 + wt * 32;
        #pragma unroll
        for (int i = 0; i < 32; ++i) dump[i] = acc[i];
    }
    __syncthreads();

    if (gid == 0) {
        #pragma unroll
        for (int g2 = 0; g2 < 3; ++g2) {
            const ull* src = (const ull*)(smem + SM_COEF) + (size_t)g2 * 4096 + wt * 32;
            #pragma unroll
            for (int i = 0; i < 32; ++i) acc[i] = addf2(acc[i], src[i]);
        }
        float s[8];
        #pragma unroll
        for (int k = 0; k < 8; ++k) s[k] = sall_s[dq * 8 + k];

        #pragma unroll
        for (int i = 0; i < 8; ++i) {
            int n = nq * 8 + i;
            if (root_s[n] > 0.f) {
                float Z = (float)NN + z_s[n] + z_s[128 + n] + z_s[256 + n] + z_s[384 + n];
                float invZ = __fdividef(1.f, Z);
                float x0, x1, x2, x3, x4, x5, x6, x7;
                unpack2(acc[i * 4 + 0], x0, x1);
                unpack2(acc[i * 4 + 1], x2, x3);
                unpack2(acc[i * 4 + 2], x4, x5);
                unpack2(acc[i * 4 + 3], x6, x7);
                float* ho = g_h + ((size_t)b * NN + nbase + n) * 64 + dq * 8;
                ((float4*)ho)[0] = make_float4((s[0] + x0) * invZ, (s[1] + x1) * invZ,
                                               (s[2] + x2) * invZ, (s[3] + x3) * invZ);
                ((float4*)ho)[1] = make_float4((s[4] + x4) * invZ, (s[5] + x5) * invZ,
                                               (s[6] + x6) * invZ, (s[7] + x7) * invZ);
            }
        }
    }
}

// ---------------- kernel 5: masked attention pool + BN-MLP head -------------
__global__ void __launch_bounds__(128) head_kernel(
    const float* __restrict__ root_list, const float* __restrict__ P,
    const float* __restrict__ pW1, const float* __restrict__ pb1,
    const float* __restrict__ g1,  const float* __restrict__ be1,
    const float* __restrict__ m1,  const float* __restrict__ v1,
    const float* __restrict__ pW2, const float* __restrict__ pb2,
    const float* __restrict__ g2,  const float* __restrict__ be2,
    const float* __restrict__ m2,  const float* __restrict__ v2,
    const float* __restrict__ pW3, const float* __restrict__ pb3,
    float* __restrict__ out) {

    __shared__ float  sh_w[NN];
    __shared__ float  sh_red[128];
    __shared__ float4 sh_part[8 * 16];
    __shared__ float  sh_pool[64];
    __shared__ float  sh_x1[128];
    __shared__ float  sh_x2[64];
    __shared__ float4 sh_P[16];

    int b = blockIdx.x;
    int tid = threadIdx.x;
    if (tid < 16) sh_P[tid] = ((const float4*)P)[tid];
    __syncthreads();

    float wsum = 0.f;
    for (int n = tid; n < NN; n += 128) {
        const float4* hr = (const float4*)(g_h + ((size_t)b * NN + n) * 64);
        float s = 0.f;
        #pragma unroll
        for (int k = 0; k < 16; ++k) {
            float4 h4 = hr[k]; float4 p4 = sh_P[k];
            s = fmaf(h4.x, p4.x, s);
            s = fmaf(h4.y, p4.y, s);
            s = fmaf(h4.z, p4.z, s);
            s = fmaf(h4.w, p4.w, s);
        }
        s = fmaxf(s, 0.f);
        float root = root_list[b * (4 * NN) + 1 * NN + n];
        float wv = (root > 0.f) ? __expf(s) : 0.f;
        sh_w[n] = wv;
        wsum += wv;
    }
    sh_red[tid] = wsum;
    __syncthreads();
    for (int o = 64; o > 0; o >>= 1) {
        if (tid < o) sh_red[tid] += sh_red[tid + o];
        __syncthreads();
    }
    float invw = __fdividef(1.f, sh_red[0]);

    {
        int dq = tid & 15, grp = tid >> 4;
        const float4* hb = (const float4*)(g_h + (size_t)b * NN * 64);
        float4 a = make_float4(0.f, 0.f, 0.f, 0.f);
        #pragma unroll 4
        for (int it = 0; it < 128; ++it) {
            int n = grp + it * 8;
            float wv = sh_w[n];
            float4 h4 = hb[n * 16 + dq];
            a.x = fmaf(wv, h4.x, a.x);
            a.y = fmaf(wv, h4.y, a.y);
            a.z = fmaf(wv, h4.z, a.z);
            a.w = fmaf(wv, h4.w, a.w);
        }
        sh_part[grp * 16 + dq] = a;
    }
    __syncthreads();
    if (tid < 64) {
        int dq = tid >> 2, comp = tid & 3;
        float acc = 0.f;
        #pragma unroll
        for (int g = 0; g < 8; ++g) {
            const float* p = (const float*)&sh_part[g * 16 + dq];
            acc += p[comp];
        }
        sh_pool[dq * 4 + comp] = acc * invw;
    }
    __syncthreads();

    {
        float acc = pb1[tid];
        #pragma unroll 8
        for (int k = 0; k < 64; ++k) acc = fmaf(sh_pool[k], pW1[k * 128 + tid], acc);
        float bnv = (acc - m1[tid]) * rsqrtf(v1[tid] + BN_EPS) * g1[tid] + be1[tid];
        sh_x1[tid] = fmaxf(bnv, 0.f);
    }
    __syncthreads();

    if (tid < 64) {
        float acc = pb2[tid];
        #pragma unroll 8
        for (int k = 0; k < 128; ++k) acc = fmaf(sh_x1[k], pW2[k * 64 + tid], acc);
        float bnv = (acc - m2[tid]) * rsqrtf(v2[tid] + BN_EPS) * g2[tid] + be2[tid];
        sh_x2[tid] = fmaxf(bnv, 0.f);
    }
    __syncthreads();

    if (tid == 0) {
        float l0 = pb3[0], l1 = pb3[1];
        #pragma unroll 8
        for (int k = 0; k < 64; ++k) {
            l0 = fmaf(sh_x2[k], pW3[k * 2 + 0], l0);
            l1 = fmaf(sh_x2[k], pW3[k * 2 + 1], l1);
        }
        l0 = fmaxf(l0, 0.f); l1 = fmaxf(l1, 0.f);
        float mx = fmaxf(l0, l1);
        float e0 = __expf(l0 - mx), e1 = __expf(l1 - mx);
        float inv = __fdividef(1.f, e0 + e1);
        out[b * 2 + 0] = e0 * inv;
        out[b * 2 + 1] = e1 * inv;
    }
}

// ---------------- launch -----------------------------------------------------
extern "C" void kernel_launch(void* const* d_in, const int* in_sizes, int n_in,
                              void* d_out, int out_size) {
    const int*   adj       = (const int*)  d_in[0];
    const float* X         = (const float*)d_in[1];
    const float* root_list = (const float*)d_in[2];
    const float* W0        = (const float*)d_in[3];
    const float* Wl        = (const float*)d_in[4];
    const float* a1l       = (const float*)d_in[5];
    const float* a2l       = (const float*)d_in[6];
    const float* P         = (const float*)d_in[7];
    const float* pW1 = (const float*)d_in[8];  const float* pb1 = (const float*)d_in[9];
    const float* g1  = (const float*)d_in[10]; const float* be1 = (const float*)d_in[11];
    const float* m1  = (const float*)d_in[12]; const float* v1  = (const float*)d_in[13];
    const float* pW2 = (const float*)d_in[14]; const float* pb2 = (const float*)d_in[15];
    const float* g2  = (const float*)d_in[16]; const float* be2 = (const float*)d_in[17];
    const float* m2  = (const float*)d_in[18]; const float* v2  = (const float*)d_in[19];
    const float* pW3 = (const float*)d_in[20]; const float* pb3 = (const float*)d_in[21];
    float* out = (float*)d_out;

    cudaFuncSetAttribute(attn_kernel, cudaFuncAttributeMaxDynamicSharedMemorySize,
                         SM_ATTN_TOTAL);

    pack_adj_kernel<<<BB * 8, 256>>>(adj);
    input_proj_kernel<<<BB * NN / 64, 256>>>(X, W0);

    for (int li = 0; li < 3; ++li) {
        hw_kernel<<<BB * NN / 64, 256>>>(Wl, a1l, a2l, li);
        attn_kernel<<<BB * 8, 512, SM_ATTN_TOTAL>>>(root_list, 3 - li, li);
    }

    head_kernel<<<BB, 128>>>(root_list, P,
                             pW1, pb1, g1, be1, m1, v1,
                             pW2, pb2, g2, be2, m2, v2,
                             pW3, pb3, out);
}